// round 11
// baseline (speedup 1.0000x reference)
#include <cuda_runtime.h>
#include <math.h>
#include <stdint.h>

// R11: 64 CTAs x 2 batches each (dual-accumulator MLP; weights delivered once
// per CTA serve 2 batch rows -> delivered bytes halved). Cluster-4 multicast
// producer warp; 67 tiles <=56KB; raster 1568px on 800 thr (2 px/thread).

#define TPB 832
#define NC 512
#define NGATE 800
#define CLUSTER 4
#define NSTAGES 3
#define SLOT_BYTES 57344
#define SLOT_FLOATS 14336
#define NT 67
#define HALFC 14.0f
#define SCALEC 12.0f

#define OUT_R  0
#define OUT_MU (128*784)
#define OUT_LV (OUT_MU + 128*64)
#define OUT_CP (OUT_LV + 128*64)
#define OUT_W  (OUT_CP + 128*64)
#define OUT_A  (OUT_W + 128*2)

struct WPtrs {
    const float *ew1, *ew2, *muw, *lvw, *dw1, *dw2, *cpw, *wdw, *alw, *rw1, *rw2;
};

__device__ __forceinline__ uint32_t smem_u32(const void* p) {
    return (uint32_t)__cvta_generic_to_shared(p);
}
__device__ __forceinline__ void mbar_init(uint32_t a, uint32_t c) {
    asm volatile("mbarrier.init.shared.b64 [%0], %1;" :: "r"(a), "r"(c) : "memory");
}
__device__ __forceinline__ void mbar_wait(uint32_t a, uint32_t par) {
    asm volatile(
        "{\n\t.reg .pred P;\nW_%=:\n\t"
        "mbarrier.try_wait.parity.acquire.cta.shared::cta.b64 P, [%0], %1, 0x989680;\n\t"
        "@P bra.uni D_%=;\n\tbra.uni W_%=;\nD_%=:\n\t}"
        :: "r"(a), "r"(par) : "memory");
}
__device__ __forceinline__ void mbar_expect_tx(uint32_t a, uint32_t b) {
    asm volatile("mbarrier.arrive.expect_tx.shared.b64 _, [%0], %1;" :: "r"(a), "r"(b) : "memory");
}
__device__ __forceinline__ void mbar_arrive_rank(uint32_t a, uint32_t r) {
    asm volatile(
        "{\n\t.reg .b32 ra;\n\tmapa.shared::cluster.u32 ra, %0, %1;\n\t"
        "mbarrier.arrive.shared::cluster.b64 _, [ra];\n\t}"
        :: "r"(a), "r"(r) : "memory");
}
__device__ __forceinline__ void cluster_sync_all() {
    asm volatile("barrier.cluster.arrive.aligned;" ::: "memory");
    asm volatile("barrier.cluster.wait.aligned;" ::: "memory");
}
__device__ __forceinline__ void bulk_mc(uint32_t d, const void* s, uint32_t b,
                                        uint32_t m, uint16_t msk) {
    asm volatile(
        "cp.async.bulk.shared::cluster.global.mbarrier::complete_tx::bytes.multicast::cluster "
        "[%0], [%1], %2, [%3], %4;"
        :: "r"(d), "l"(s), "r"(b), "r"(m), "h"(msk) : "memory");
}

__device__ __forceinline__ float seluf(float x) {
    const float sc = 1.0507009873554805f, al = 1.6732632423543772f;
    return x > 0.0f ? sc * x : sc * al * (expf(x) - 1.0f);
}
__device__ __forceinline__ float lrelu(float x) { return x >= 0.0f ? x : 0.2f * x; }
__device__ __forceinline__ float sigm(float x)  { return 1.0f / (1.0f + expf(-x)); }

// Tile table, 67 tiles, slot 57344B:
//  0-13  enc1 14x56rows   14-18 enc2 {56,56,56,56,32}
//  19-20 muw 2x32KB       21-22 lvw 2x32KB
//  23-26 dw1 4x16rows     27-58 dw2 32x16rows
//  59 cpw 57344           60 wdw+alw
//  61-64 rw1 {28,28,28,8} 65-66 rw2 2x53248
__device__ __forceinline__ int tile_segs(int n, const WPtrs& p,
                                         const char* srcs[2], uint32_t szs[2]) {
    if (n < 14) { srcs[0] = (const char*)(p.ew1 + n * 56 * 256); szs[0] = 57344; return 1; }
    n -= 14;
    if (n < 5)  { int rows = (n < 4) ? 56 : 32;
                  srcs[0] = (const char*)(p.ew2 + n * 56 * 256); szs[0] = rows * 1024; return 1; }
    n -= 5;
    if (n < 2)  { srcs[0] = (const char*)(p.muw + n * 128 * 64); szs[0] = 32768; return 1; }
    n -= 2;
    if (n < 2)  { srcs[0] = (const char*)(p.lvw + n * 128 * 64); szs[0] = 32768; return 1; }
    n -= 2;
    if (n < 4)  { srcs[0] = (const char*)(p.dw1 + n * 16 * 512); szs[0] = 32768; return 1; }
    n -= 4;
    if (n < 32) { srcs[0] = (const char*)(p.dw2 + n * 16 * 512); szs[0] = 32768; return 1; }
    n -= 32;
    if (n == 0) { srcs[0] = (const char*)p.cpw; szs[0] = 57344; return 1; } n--;
    if (n == 0) { srcs[0] = (const char*)p.wdw; szs[0] = 4096;
                  srcs[1] = (const char*)p.alw; szs[1] = 4096; return 2; } n--;
    if (n < 4)  { int rows = (n < 3) ? 28 : 8;
                  srcs[0] = (const char*)(p.rw1 + n * 28 * 512); szs[0] = rows * 2048; return 1; }
    n -= 4;
    srcs[0] = (const char*)(p.rw2 + n * 256 * 52); szs[0] = 53248; return 1;
}

__device__ __forceinline__ void produce(int j, uint32_t bar_base, uint32_t ring_base,
                                        const WPtrs& p, uint32_t rank) {
    const int s = j % NSTAGES;
    mbar_wait(bar_base + s * 16 + 8, 1u ^ ((uint32_t)(j / NSTAGES) & 1u));
    const char* srcs[2]; uint32_t szs[2];
    int ns = tile_segs(j, p, srcs, szs);
    uint32_t total = szs[0] + ((ns > 1) ? szs[1] : 0u);
    const uint32_t full = bar_base + s * 16;
    mbar_expect_tx(full, total);
    uint32_t dst = ring_base + s * SLOT_BYTES;
    for (int k = 0; k < ns; k++) {
        uint32_t slice = szs[k] >> 2;
        bulk_mc(dst + rank * slice, srcs[k] + rank * slice, slice, full, 0xF);
        dst += szs[k];
    }
}

#define CONS_SYNC() asm volatile("bar.sync 1, %0;" :: "n"(NC) : "memory")
#define GATE_SYNC() asm volatile("bar.sync 2, %0;" :: "n"(NGATE) : "memory")
#define TILE_BEGIN() do { \
        mbar_wait(bar_base + (tn % NSTAGES) * 16, (uint32_t)(tn / NSTAGES) & 1u); \
        ws = wb + (tn % NSTAGES) * SLOT_FLOATS; } while (0)
#define TILE_END() do { __syncwarp(); \
        if ((tid & 31) == 0) { uint32_t e = bar_base + (tn % NSTAGES) * 16 + 8; \
            mbar_arrive_rank(e, 0); mbar_arrive_rank(e, 1); \
            mbar_arrive_rank(e, 2); mbar_arrive_rank(e, 3); } \
        tn++; } while (0)

// dual-batch FMA step on 4 cols
#define DUAL4(av0, av1, w4) do { \
        a00 = fmaf(av0, w4.x, a00); a01 = fmaf(av0, w4.y, a01); \
        a02 = fmaf(av0, w4.z, a02); a03 = fmaf(av0, w4.w, a03); \
        a10 = fmaf(av1, w4.x, a10); a11 = fmaf(av1, w4.y, a11); \
        a12 = fmaf(av1, w4.z, a12); a13 = fmaf(av1, w4.w, a13); } while (0)

__global__ void __launch_bounds__(TPB, 1) __cluster_dims__(CLUSTER, 1, 1)
fused_kernel(
    const float* __restrict__ x,    const float* __restrict__ eps,
    const float* __restrict__ ew1,  const float* __restrict__ eb1,
    const float* __restrict__ ew2,  const float* __restrict__ eb2,
    const float* __restrict__ muw,  const float* __restrict__ mub,
    const float* __restrict__ lvw,  const float* __restrict__ lvb,
    const float* __restrict__ dw1,  const float* __restrict__ db1,
    const float* __restrict__ dw2,  const float* __restrict__ db2,
    const float* __restrict__ cpw,  const float* __restrict__ cpb,
    const float* __restrict__ rw1,  const float* __restrict__ rb1,
    const float* __restrict__ rw2w, const float* __restrict__ rb2,
    const float* __restrict__ wdw,  const float* __restrict__ wdb,
    const float* __restrict__ alw,  const float* __restrict__ alb,
    float* __restrict__ out)
{
    extern __shared__ float wb[];
    const int b0  = blockIdx.x * 2;
    const int tid = threadIdx.x;

    __shared__ alignas(16) unsigned long long mbars[NSTAGES * 2];
    __shared__ alignas(16) float x4[1568];
    __shared__ float h1[512], h2[512];       // [bb*256+c]
    __shared__ float muv[128];               // [bb*64+l]
    __shared__ float hin[184];               // [bb*92+..]
    __shared__ float d1[1024], d2[1024], r1[1024]; // [bb*512+c]
    __shared__ float pts[104];               // [bb*52+c]
    __shared__ alignas(16) float red[2048], red2[2048];
    __shared__ float qx[128], qy[128], wa[8];
    __shared__ alignas(16) float4 pt4[128];

    WPtrs wp; wp.ew1 = ew1; wp.ew2 = ew2; wp.muw = muw; wp.lvw = lvw;
    wp.dw1 = dw1; wp.dw2 = dw2; wp.cpw = cpw; wp.wdw = wdw; wp.alw = alw;
    wp.rw1 = rw1; wp.rw2 = rw2w;

    const uint32_t bar_base  = smem_u32(mbars);
    const uint32_t ring_base = smem_u32(wb);
    uint32_t rank;
    asm("mov.u32 %0, %%cluster_ctarank;" : "=r"(rank));

    if (tid == 0) {
        #pragma unroll
        for (int s = 0; s < NSTAGES; s++) {
            mbar_init(bar_base + s * 16, 1);
            mbar_init(bar_base + s * 16 + 8, 64);
        }
    }
    __syncthreads();
    cluster_sync_all();

    if (tid >= NGATE) {
        if (tid == NGATE) {
            for (int j = 0; j < NT; j++) produce(j, bar_base, ring_base, wp, rank);
        }
    } else {
        if (tid < NC) {
            for (int i = tid; i < 1568; i += NC) x4[i] = x[b0 * 784 + i];
            CONS_SYNC();

            int tn = 0;
            float* ws;

            // enc1: 14 tiles x 56 rows; kg 8-way (7 rows/tile), 4 cols, dual batch
            {
                const int kg = tid >> 6, q = (tid & 63) * 4;
                float a00 = 0, a01 = 0, a02 = 0, a03 = 0, a10 = 0, a11 = 0, a12 = 0, a13 = 0;
                for (int t = 0; t < 14; t++) {
                    TILE_BEGIN();
                    const int rb = kg * 7, gr = t * 56 + rb;
                    #pragma unroll
                    for (int r = 0; r < 7; r++) {
                        const float av0 = x4[gr + r], av1 = x4[784 + gr + r];
                        const float4 w4 = *(const float4*)&ws[(rb + r) * 256 + q];
                        DUAL4(av0, av1, w4);
                    }
                    TILE_END();
                }
                *(float4*)&red[kg * 256 + q]  = make_float4(a00, a01, a02, a03);
                *(float4*)&red2[kg * 256 + q] = make_float4(a10, a11, a12, a13);
            }
            CONS_SYNC();
            {
                const int bb = tid >> 8, c = tid & 255;
                const float* rp = bb ? red2 : red;
                float s = eb1[c];
                #pragma unroll
                for (int k = 0; k < 8; k++) s += rp[k * 256 + c];
                h1[bb * 256 + c] = lrelu(s);
            }
            CONS_SYNC();

            // enc2: 5 tiles {56,56,56,56,32}; kg 8-way, dual
            {
                const int kg = tid >> 6, q = (tid & 63) * 4;
                float a00 = 0, a01 = 0, a02 = 0, a03 = 0, a10 = 0, a11 = 0, a12 = 0, a13 = 0;
                for (int t = 0; t < 5; t++) {
                    TILE_BEGIN();
                    const int per = (t < 4) ? 7 : 4;
                    const int rb = kg * per, gr = t * 56 + rb;
                    #pragma unroll
                    for (int r = 0; r < per; r++) {
                        const float av0 = h1[gr + r], av1 = h1[256 + gr + r];
                        const float4 w4 = *(const float4*)&ws[(rb + r) * 256 + q];
                        DUAL4(av0, av1, w4);
                    }
                    TILE_END();
                }
                *(float4*)&red[kg * 256 + q]  = make_float4(a00, a01, a02, a03);
                *(float4*)&red2[kg * 256 + q] = make_float4(a10, a11, a12, a13);
            }
            CONS_SYNC();
            {
                const int bb = tid >> 8, c = tid & 255;
                const float* rp = bb ? red2 : red;
                float s = eb2[c];
                #pragma unroll
                for (int k = 0; k < 8; k++) s += rp[k * 256 + c];
                h2[bb * 256 + c] = lrelu(s);
            }
            CONS_SYNC();

            // mu: 2 tiles x 128 rows; g 8-way (16 rows/tile), dual
            {
                const int g = tid >> 6, l = tid & 63;
                float a0 = 0, a1 = 0;
                for (int t = 0; t < 2; t++) {
                    TILE_BEGIN();
                    #pragma unroll 8
                    for (int i = 0; i < 16; i++) {
                        const int rl = g * 16 + i, gr = t * 128 + rl;
                        const float w = ws[rl * 64 + l];
                        a0 = fmaf(h2[gr], w, a0); a1 = fmaf(h2[256 + gr], w, a1);
                    }
                    TILE_END();
                }
                red[tid] = a0; red2[tid] = a1;
            }
            CONS_SYNC();
            if (tid < 128) {
                const int bb = tid >> 6, l = tid & 63;
                const float* rp = bb ? red2 : red;
                float s = mub[l];
                #pragma unroll
                for (int k = 0; k < 8; k++) s += rp[k * 64 + l];
                muv[bb * 64 + l] = s;
            }
            CONS_SYNC();

            // logvar: 2 tiles
            {
                const int g = tid >> 6, l = tid & 63;
                float a0 = 0, a1 = 0;
                for (int t = 0; t < 2; t++) {
                    TILE_BEGIN();
                    #pragma unroll 8
                    for (int i = 0; i < 16; i++) {
                        const int rl = g * 16 + i, gr = t * 128 + rl;
                        const float w = ws[rl * 64 + l];
                        a0 = fmaf(h2[gr], w, a0); a1 = fmaf(h2[256 + gr], w, a1);
                    }
                    TILE_END();
                }
                red[tid] = a0; red2[tid] = a1;
            }
            CONS_SYNC();
            if (tid < 128) {
                const int bb = tid >> 6, l = tid & 63;
                const float* rp = bb ? red2 : red;
                float lvV = lvb[l];
                #pragma unroll
                for (int k = 0; k < 8; k++) lvV += rp[k * 64 + l];
                float m = muv[bb * 64 + l];
                out[OUT_MU + (b0 + bb) * 64 + l] = m;
                out[OUT_LV + (b0 + bb) * 64 + l] = lvV;
                hin[bb * 92 + l] = m + eps[(b0 + bb) * 64 + l] * expf(0.5f * lvV);
            }
            CONS_SYNC();

            // dec1: 4 tiles x 16 rows; kg 4-way (4 rows/tile), dual
            {
                const int kg = tid >> 7, q = (tid & 127) * 4;
                float a00 = 0, a01 = 0, a02 = 0, a03 = 0, a10 = 0, a11 = 0, a12 = 0, a13 = 0;
                for (int t = 0; t < 4; t++) {
                    TILE_BEGIN();
                    const int rb = kg * 4, gr = t * 16 + rb;
                    #pragma unroll
                    for (int r = 0; r < 4; r++) {
                        const float av0 = hin[gr + r], av1 = hin[92 + gr + r];
                        const float4 w4 = *(const float4*)&ws[(rb + r) * 512 + q];
                        DUAL4(av0, av1, w4);
                    }
                    TILE_END();
                }
                *(float4*)&red[kg * 512 + q]  = make_float4(a00, a01, a02, a03);
                *(float4*)&red2[kg * 512 + q] = make_float4(a10, a11, a12, a13);
            }
            CONS_SYNC();
            {
                float s0 = db1[tid] + ((red[tid] + red[512 + tid]) + (red[1024 + tid] + red[1536 + tid]));
                float s1 = db1[tid] + ((red2[tid] + red2[512 + tid]) + (red2[1024 + tid] + red2[1536 + tid]));
                d1[tid] = seluf(s0); d1[512 + tid] = seluf(s1);
            }
            CONS_SYNC();

            // dec2: 32 tiles x 16 rows; kg 4-way, dual
            {
                const int kg = tid >> 7, q = (tid & 127) * 4;
                float a00 = 0, a01 = 0, a02 = 0, a03 = 0, a10 = 0, a11 = 0, a12 = 0, a13 = 0;
                for (int t = 0; t < 32; t++) {
                    TILE_BEGIN();
                    const int rb = kg * 4, gr = t * 16 + rb;
                    #pragma unroll
                    for (int r = 0; r < 4; r++) {
                        const float av0 = d1[gr + r], av1 = d1[512 + gr + r];
                        const float4 w4 = *(const float4*)&ws[(rb + r) * 512 + q];
                        DUAL4(av0, av1, w4);
                    }
                    TILE_END();
                }
                *(float4*)&red[kg * 512 + q]  = make_float4(a00, a01, a02, a03);
                *(float4*)&red2[kg * 512 + q] = make_float4(a10, a11, a12, a13);
            }
            CONS_SYNC();
            {
                float s0 = db2[tid] + ((red[tid] + red[512 + tid]) + (red[1024 + tid] + red[1536 + tid]));
                float s1 = db2[tid] + ((red2[tid] + red2[512 + tid]) + (red2[1024 + tid] + red2[1536 + tid]));
                d2[tid] = seluf(s0); d2[512 + tid] = seluf(s1);
            }
            CONS_SYNC();

            // coarse cp: 1 tile 512x28; g 16-way (32 rows), dual
            {
                const int g = tid >> 5, l = tid & 31;
                TILE_BEGIN();
                float a0 = 0, a1 = 0;
                if (l < 28) {
                    #pragma unroll 8
                    for (int i = 0; i < 32; i++) {
                        const int kl = g * 32 + i;
                        const float w = ws[kl * 28 + l];
                        a0 = fmaf(d2[kl], w, a0); a1 = fmaf(d2[512 + kl], w, a1);
                    }
                }
                red[tid] = a0; red2[tid] = a1;
                TILE_END();
            }
            CONS_SYNC();
            if (tid < 28 || (tid >= 32 && tid < 60)) {
                const int bb = tid >> 5, c = tid & 31;
                const float* rp = bb ? red2 : red;
                float s = cpb[c];
                #pragma unroll
                for (int k = 0; k < 16; k++) s += rp[k * 32 + c];
                hin[bb * 92 + 64 + c] = tanhf(s);
            }
            CONS_SYNC();

            // widths + alphas: 1 tile; dual
            {
                const int pp = tid >> 8, l = tid & 255;
                TILE_BEGIN();
                float aw0 = 0, aa0 = 0, aw1 = 0, aa1 = 0;
                #pragma unroll
                for (int k = 0; k < 2; k++) {
                    const int i = l + k * 256;
                    const float ww = ws[i * 2 + pp], wA = ws[1024 + i * 2 + pp];
                    aw0 = fmaf(d2[i], ww, aw0); aa0 = fmaf(d2[i], wA, aa0);
                    aw1 = fmaf(d2[512 + i], ww, aw1); aa1 = fmaf(d2[512 + i], wA, aa1);
                }
                red[tid] = aw0; red[1024 + tid] = aw1;
                red2[tid] = aa0; red2[1024 + tid] = aa1;
                TILE_END();
            }
            CONS_SYNC();
            {
                const int grp = tid >> 5;           // 0:w b0, 1:a b0, 2:w b1, 3:a b1
                const int pp = tid & 31;
                if (grp < 4 && pp < 2) {
                    const int bb = grp >> 1, isA = grp & 1;
                    const float* rp = (isA ? red2 : red) + bb * 1024 + pp * 256;
                    float s0 = 0, s1 = 0, s2 = 0, s3 = 0;
                    #pragma unroll
                    for (int j = 0; j < 64; j++) { s0 += rp[j]; s1 += rp[64 + j]; s2 += rp[128 + j]; s3 += rp[192 + j]; }
                    float tot = (s0 + s1) + (s2 + s3);
                    if (isA) {
                        float av = sigm(alb[pp] + tot);
                        wa[bb * 4 + 2 + pp] = av;
                        out[OUT_A + (b0 + bb) * 2 + pp] = av;
                    } else {
                        float wv = sigm(wdb[pp] + tot) * 2.0f + 1.0f;
                        wa[bb * 4 + pp] = wv;
                        out[OUT_W + (b0 + bb) * 2 + pp] = wv;
                    }
                }
            }
            CONS_SYNC();

            // refine1: 4 tiles {28,28,28,8}; kg 4-way, dual
            {
                const int kg = tid >> 7, q = (tid & 127) * 4;
                float a00 = 0, a01 = 0, a02 = 0, a03 = 0, a10 = 0, a11 = 0, a12 = 0, a13 = 0;
                for (int t = 0; t < 4; t++) {
                    TILE_BEGIN();
                    const int per = (t < 3) ? 7 : 2;
                    const int rb = kg * per, gr = t * 28 + rb;
                    #pragma unroll
                    for (int r = 0; r < per; r++) {
                        const float av0 = hin[gr + r], av1 = hin[92 + gr + r];
                        const float4 w4 = *(const float4*)&ws[(rb + r) * 512 + q];
                        DUAL4(av0, av1, w4);
                    }
                    TILE_END();
                }
                *(float4*)&red[kg * 512 + q]  = make_float4(a00, a01, a02, a03);
                *(float4*)&red2[kg * 512 + q] = make_float4(a10, a11, a12, a13);
            }
            CONS_SYNC();
            {
                float s0 = rb1[tid] + ((red[tid] + red[512 + tid]) + (red[1024 + tid] + red[1536 + tid]));
                float s1 = rb1[tid] + ((red2[tid] + red2[512 + tid]) + (red2[1024 + tid] + red2[1536 + tid]));
                r1[tid] = seluf(s0); r1[512 + tid] = seluf(s1);
            }
            CONS_SYNC();

            // refine2: 2 tiles x 256 rows; g 8-way (32 rows/tile), dual
            {
                const int g = tid >> 6, l = tid & 63;
                float a0 = 0, a1 = 0;
                for (int t = 0; t < 2; t++) {
                    TILE_BEGIN();
                    if (l < 52) {
                        #pragma unroll 8
                        for (int i = 0; i < 32; i++) {
                            const int kl = g * 32 + i, gr = t * 256 + kl;
                            const float w = ws[kl * 52 + l];
                            a0 = fmaf(r1[gr], w, a0); a1 = fmaf(r1[512 + gr], w, a1);
                        }
                    }
                    TILE_END();
                }
                red[tid] = a0; red2[tid] = a1;
            }
            CONS_SYNC();
            if ((tid & 63) < 52 && tid < 128) {
                const int bb = tid >> 6, c = tid & 63;
                const float* rp = bb ? red2 : red;
                float s = rb2[c];
                #pragma unroll
                for (int k = 0; k < 8; k++) s += rp[k * 64 + c];
                pts[bb * 52 + c] = tanhf(s) * SCALEC + HALFC;
            }
            CONS_SYNC();

            // control points out + bezier sample eval (both batches)
            if (tid < 128) {
                const int bb = tid >> 6, idx = tid & 63;
                const int p = idx >> 5, rem = idx & 31;
                const float* pb = pts + bb * 52;
                {
                    int s = rem >> 3, k = (rem >> 1) & 3, d = rem & 1;
                    out[OUT_CP + (b0 + bb) * 64 + idx] = pb[p * 26 + (3 * s + k) * 2 + d];
                }
                const int ss = rem >> 3, ti = rem & 7;
                float t  = (float)ti / 7.0f;
                float mt = 1.0f - t;
                float c0 = mt * mt * mt, c1 = 3.0f * mt * mt * t;
                float c2 = 3.0f * mt * t * t, c3 = t * t * t;
                int base = p * 26 + (3 * ss) * 2;
                float X = c0 * pb[base + 0] + c1 * pb[base + 2] + c2 * pb[base + 4] + c3 * pb[base + 6];
                float Y = c0 * pb[base + 1] + c1 * pb[base + 3] + c2 * pb[base + 5] + c3 * pb[base + 7];
                qx[tid] = X; qy[tid] = Y;
            }
            CONS_SYNC();
            if (tid < 128) {
                const int bb = tid >> 6, idx = tid & 63;
                const int p = idx >> 5, m = idx & 31;
                float X = qx[tid], Y = qy[tid];
                float y1 = qy[bb * 64 + p * 32 + ((m + 1) & 31)];
                float si = __fdiv_rn(1.0f, (y1 - Y) + 1e-8f);
                pt4[tid] = make_float4(X, Y, X * X + Y * Y, si);
            }
        }

        GATE_SYNC();

        // rasterizer: 1568 px over 800 threads
        for (int kk = 0; kk < 2; kk++) {
            const int idx = tid + kk * NGATE;
            if (idx >= 1568) break;
            const int bb = (idx >= 784) ? 1 : 0;
            const int px = idx - bb * 784;
            const int pi = px / 28, pj = px - pi * 28;
            float syv[4], sxv[4], nxv[4], nyv[4], ssn[4], val[4];
            #pragma unroll
            for (int s = 0; s < 4; s++) {
                syv[s] = (float)pi + (0.25f + 0.5f * (float)(s >> 1));
                sxv[s] = (float)pj + (0.25f + 0.5f * (float)(s & 1));
                nxv[s] = -2.0f * sxv[s]; nyv[s] = -2.0f * syv[s];
                ssn[s] = sxv[s] * sxv[s] + syv[s] * syv[s];
                val[s] = 1.0f;
            }
            #pragma unroll
            for (int p = 0; p < 2; p++) {
                const int base = bb * 64 + p * 32;
                float mind2[4]; int nc[4]; bool cb[4];
                float4 e = pt4[base];
                #pragma unroll
                for (int s = 0; s < 4; s++) { mind2[s] = 3.402823e38f; nc[s] = 0; cb[s] = e.y > syv[s]; }
                #pragma unroll 8
                for (int m = 0; m < 32; m++) {
                    const float4 e1 = pt4[base + ((m + 1) & 31)];
                    const float dx = e1.x - e.x;
                    #pragma unroll
                    for (int s = 0; s < 4; s++) {
                        float v = fmaf(nxv[s], e.x, fmaf(nyv[s], e.y, e.z + ssn[s]));
                        mind2[s] = fminf(mind2[s], v);
                        const bool c1 = e1.y > syv[s];
                        const float xint = fmaf((syv[s] - e.y) * e.w, dx, e.x);
                        nc[s] += (int)((cb[s] != c1) && (sxv[s] < xint));
                        cb[s] = c1;
                    }
                    e = e1;
                }
                #pragma unroll
                for (int s = 0; s < 4; s++) {
                    const float dist   = sqrtf(fmaxf(mind2[s], 0.0f));
                    const float stroke = fminf(fmaxf(fmaf(wa[bb * 4 + p], 0.5f, 0.5f) - dist, 0.0f), 1.0f);
                    const float cov    = fmaxf((float)(nc[s] & 1), stroke);
                    val[s] *= 1.0f - wa[bb * 4 + 2 + p] * cov;
                }
            }
            const float acc = (val[0] + val[1]) + (val[2] + val[3]);
            out[OUT_R + (b0 + bb) * 784 + px] = 1.0f - 0.25f * acc;
        }
    }

    cluster_sync_all();
}

extern "C" void kernel_launch(void* const* d_in, const int* in_sizes, int n_in,
                              void* d_out, int out_size)
{
    const float* x    = (const float*)d_in[0];
    const float* eps  = (const float*)d_in[1];
    const float* ew1  = (const float*)d_in[2];
    const float* eb1  = (const float*)d_in[3];
    const float* ew2  = (const float*)d_in[4];
    const float* eb2  = (const float*)d_in[5];
    const float* muw  = (const float*)d_in[6];
    const float* mub  = (const float*)d_in[7];
    const float* lvw  = (const float*)d_in[8];
    const float* lvb  = (const float*)d_in[9];
    const float* dw1  = (const float*)d_in[10];
    const float* db1  = (const float*)d_in[11];
    const float* dw2  = (const float*)d_in[12];
    const float* db2  = (const float*)d_in[13];
    const float* cpw  = (const float*)d_in[14];
    const float* cpb  = (const float*)d_in[15];
    const float* rw1  = (const float*)d_in[16];
    const float* rb1  = (const float*)d_in[17];
    const float* rw2  = (const float*)d_in[18];
    const float* rb2  = (const float*)d_in[19];
    const float* wdw  = (const float*)d_in[20];
    const float* wdb  = (const float*)d_in[21];
    const float* alw  = (const float*)d_in[22];
    const float* alb  = (const float*)d_in[23];
    float* out = (float*)d_out;

    const int dyn = NSTAGES * SLOT_BYTES;   // 172032 bytes
    cudaFuncSetAttribute(fused_kernel, cudaFuncAttributeMaxDynamicSharedMemorySize, dyn);
    fused_kernel<<<64, TPB, dyn>>>(x, eps, ew1, eb1, ew2, eb2, muw, mub, lvw, lvb,
                                   dw1, db1, dw2, db2, cpw, cpb, rw1, rb1, rw2, rb2,
                                   wdw, wdb, alw, alb, out);
}